// round 8
// baseline (speedup 1.0000x reference)
#include <cuda_runtime.h>
#include <cuda_fp16.h>

#define BB 8
#define NN 5000
#define EE 100000
#define DD 128
#define NB (BB * NN)        // 40000
#define NE (BB * EE)        // 800000

typedef unsigned long long u64;
typedef unsigned int u32;

// Scratch (allocation-free: __device__ globals; zero-initialized at load).
// INVARIANT: g_deg is all-zero at kernel_launch entry; gather_kernel restores
// it to zero every execution (so hist can atomicAdd without a zeroing pass).
__device__ __align__(16) int   g_deg[NB];
__device__ __align__(16) int   g_off[NB];
__device__ __align__(16) int   g_cursor[NB];
__device__ __align__(16) int2  g_bin[NE];                // packed CSR bins
__device__ __align__(16) uint2 g_xh[NB * DD / 4];        // x as fp16
__device__ __align__(16) uint2 g_meanh[NB * DD / 4];     // mean as fp16

// ---------------------------------------------------------------------------
// K1: hist + prep combined (role by blockIdx).
//   blocks [0, HIST_BLOCKS)  : histogram of edge targets, 8 edges/thread
//   rest                     : convert x -> fp16 (streaming; hides in hist's
//                              atomic latency)
// g_deg needs no zeroing: zero-invariant maintained by gather_kernel.
// ---------------------------------------------------------------------------
#define HIST_BLOCKS ((NE / 8 + 255) / 256)            // 391
#define PREP_BLOCKS ((NB * DD / 4 + 255) / 256)       // 5000

__global__ void hist_prep_kernel(const float* __restrict__ x,
                                 const int* __restrict__ ei) {
    if (blockIdx.x < HIST_BLOCKS) {
        int t = blockIdx.x * blockDim.x + threadIdx.x;
        int base = t * 8;
        if (base >= NE) return;
        int b = base / EE;
        int e = base - b * EE;                 // EE % 8 == 0: never straddles b
        const int* tp = ei + (size_t)b * 2 * EE + EE;
        int4 ta = __ldg((const int4*)&tp[e]);
        int4 tb = __ldg((const int4*)&tp[e + 4]);
        int* deg = g_deg + b * NN;
        atomicAdd(&deg[ta.x], 1);
        atomicAdd(&deg[ta.y], 1);
        atomicAdd(&deg[ta.z], 1);
        atomicAdd(&deg[ta.w], 1);
        atomicAdd(&deg[tb.x], 1);
        atomicAdd(&deg[tb.y], 1);
        atomicAdd(&deg[tb.z], 1);
        atomicAdd(&deg[tb.w], 1);
    } else {
        int i = (blockIdx.x - HIST_BLOCKS) * blockDim.x + threadIdx.x;
        if (i < NB * DD / 4) {
            float4 v = __ldg(&((const float4*)x)[i]);
            __half2 h0 = __floats2half2_rn(v.x, v.y);
            __half2 h1 = __floats2half2_rn(v.z, v.w);
            g_xh[i] = make_uint2(*(u32*)&h0, *(u32*)&h1);
        }
    }
}

// ---------------------------------------------------------------------------
// K2: exclusive prefix sum over 40000 degrees. Single block, 1024 threads,
// warp-shuffle two-level scan (2 barriers instead of 40).
// ---------------------------------------------------------------------------
__global__ void __launch_bounds__(1024, 1) scan_kernel() {
    __shared__ int wsum[32];
    const int t = threadIdx.x;
    const int lane = t & 31;
    const int wid = t >> 5;
    const int CH = 40;                   // ints per thread (NB = 1024*40 - pad)
    int lo = t * CH;
    int hi = lo + CH; if (hi > NB) hi = NB;

    int local = 0;
    if (lo < NB) {
        const int4* d4 = (const int4*)(g_deg + lo);
#pragma unroll
        for (int i = 0; i < CH / 4; ++i) {
            int4 v = d4[i];
            local += v.x + v.y + v.z + v.w;
        }
    }

    // intra-warp inclusive scan
    int inc = local;
#pragma unroll
    for (int o = 1; o < 32; o <<= 1) {
        int v = __shfl_up_sync(0xFFFFFFFFu, inc, o);
        if (lane >= o) inc += v;
    }
    if (lane == 31) wsum[wid] = inc;
    __syncthreads();
    if (wid == 0) {
        int v = wsum[lane];
#pragma unroll
        for (int o = 1; o < 32; o <<= 1) {
            int u = __shfl_up_sync(0xFFFFFFFFu, v, o);
            if (lane >= o) v += u;
        }
        wsum[lane] = v;
    }
    __syncthreads();

    if (lo < NB) {
        int run = (wid > 0 ? wsum[wid - 1] : 0) + (inc - local);
        const int4* d4 = (const int4*)(g_deg + lo);
        int4* o4 = (int4*)(g_off + lo);
        int4* c4 = (int4*)(g_cursor + lo);
#pragma unroll
        for (int i = 0; i < CH / 4; ++i) {
            int4 v = d4[i];
            int4 w;
            w.x = run; run += v.x;
            w.y = run; run += v.y;
            w.z = run; run += v.z;
            w.w = run; run += v.w;
            o4[i] = w;
            c4[i] = w;
        }
    }
}

// ---------------------------------------------------------------------------
// K3: fill bins (8 edges/thread — round-6 variant, measured 17.0us)
// ---------------------------------------------------------------------------
__global__ void fill_kernel(const int* __restrict__ ei,
                            const float* __restrict__ em) {
    int t = blockIdx.x * blockDim.x + threadIdx.x;
    int base = t * 8;
    if (base >= NE) return;
    int b = base / EE;
    int e = base - b * EE;
    const int* eb = ei + (size_t)b * 2 * EE;
    int4 sa = __ldg((const int4*)&eb[e]);
    int4 sb = __ldg((const int4*)&eb[e + 4]);
    int4 ta = __ldg((const int4*)&eb[EE + e]);
    int4 tb = __ldg((const int4*)&eb[EE + e + 4]);
    float4 ma = __ldg((const float4*)&em[(size_t)b * EE + e]);
    float4 mb = __ldg((const float4*)&em[(size_t)b * EE + e + 4]);
    int* cur = g_cursor + b * NN;
    int p0 = atomicAdd(&cur[ta.x], 1);
    int p1 = atomicAdd(&cur[ta.y], 1);
    int p2 = atomicAdd(&cur[ta.z], 1);
    int p3 = atomicAdd(&cur[ta.w], 1);
    int p4 = atomicAdd(&cur[tb.x], 1);
    int p5 = atomicAdd(&cur[tb.y], 1);
    int p6 = atomicAdd(&cur[tb.z], 1);
    int p7 = atomicAdd(&cur[tb.w], 1);
    g_bin[p0] = make_int2(sa.x, __float_as_int(ma.x));
    g_bin[p1] = make_int2(sa.y, __float_as_int(ma.y));
    g_bin[p2] = make_int2(sa.z, __float_as_int(ma.z));
    g_bin[p3] = make_int2(sa.w, __float_as_int(ma.w));
    g_bin[p4] = make_int2(sb.x, __float_as_int(mb.x));
    g_bin[p5] = make_int2(sb.y, __float_as_int(mb.y));
    g_bin[p6] = make_int2(sb.z, __float_as_int(mb.z));
    g_bin[p7] = make_int2(sb.w, __float_as_int(mb.w));
}

// ---------------------------------------------------------------------------
// K4: gather. One warp per node; lane owns uint2 (4 halfs) of the 256B row
// (round-5 proven shape), deepened to 8-edge unroll for more MLP.
// Also resets g_deg[g] to 0 (zero-invariant for hist next execution).
// ---------------------------------------------------------------------------
__global__ void gather_kernel() {
    int g = (blockIdx.x * blockDim.x + threadIdx.x) >> 5;
    int lane = threadIdx.x & 31;
    if (g >= NB) return;
    int b = g / NN;

    const int deg = g_deg[g];
    const int off = g_off[g];
    if (lane == 0) g_deg[g] = 0;            // restore zero-invariant
    const uint2* xr = g_xh + (size_t)b * NN * 32;
    const int2* bin = g_bin + off;

    float4 acc = make_float4(0.f, 0.f, 0.f, 0.f);
    float cm = 0.f;

#define EDGE_FMA(u, m)                                                        \
    {                                                                         \
        float2 a = __half22float2(*(__half2*)&(u).x);                         \
        float2 c = __half22float2(*(__half2*)&(u).y);                         \
        acc.x = fmaf(a.x, (m), acc.x);                                        \
        acc.y = fmaf(a.y, (m), acc.y);                                        \
        acc.z = fmaf(c.x, (m), acc.z);                                        \
        acc.w = fmaf(c.y, (m), acc.w);                                        \
        cm += (m);                                                            \
    }

    int j = 0;
    for (; j + 8 <= deg; j += 8) {
        int2 r0 = __ldg(&bin[j]);
        int2 r1 = __ldg(&bin[j + 1]);
        int2 r2 = __ldg(&bin[j + 2]);
        int2 r3 = __ldg(&bin[j + 3]);
        int2 r4 = __ldg(&bin[j + 4]);
        int2 r5 = __ldg(&bin[j + 5]);
        int2 r6 = __ldg(&bin[j + 6]);
        int2 r7 = __ldg(&bin[j + 7]);
        uint2 u0 = __ldg(&xr[(size_t)r0.x * 32 + lane]);
        uint2 u1 = __ldg(&xr[(size_t)r1.x * 32 + lane]);
        uint2 u2 = __ldg(&xr[(size_t)r2.x * 32 + lane]);
        uint2 u3 = __ldg(&xr[(size_t)r3.x * 32 + lane]);
        uint2 u4 = __ldg(&xr[(size_t)r4.x * 32 + lane]);
        uint2 u5 = __ldg(&xr[(size_t)r5.x * 32 + lane]);
        uint2 u6 = __ldg(&xr[(size_t)r6.x * 32 + lane]);
        uint2 u7 = __ldg(&xr[(size_t)r7.x * 32 + lane]);
        EDGE_FMA(u0, __int_as_float(r0.y))
        EDGE_FMA(u1, __int_as_float(r1.y))
        EDGE_FMA(u2, __int_as_float(r2.y))
        EDGE_FMA(u3, __int_as_float(r3.y))
        EDGE_FMA(u4, __int_as_float(r4.y))
        EDGE_FMA(u5, __int_as_float(r5.y))
        EDGE_FMA(u6, __int_as_float(r6.y))
        EDGE_FMA(u7, __int_as_float(r7.y))
    }
    for (; j + 4 <= deg; j += 4) {
        int2 r0 = __ldg(&bin[j]);
        int2 r1 = __ldg(&bin[j + 1]);
        int2 r2 = __ldg(&bin[j + 2]);
        int2 r3 = __ldg(&bin[j + 3]);
        uint2 u0 = __ldg(&xr[(size_t)r0.x * 32 + lane]);
        uint2 u1 = __ldg(&xr[(size_t)r1.x * 32 + lane]);
        uint2 u2 = __ldg(&xr[(size_t)r2.x * 32 + lane]);
        uint2 u3 = __ldg(&xr[(size_t)r3.x * 32 + lane]);
        EDGE_FMA(u0, __int_as_float(r0.y))
        EDGE_FMA(u1, __int_as_float(r1.y))
        EDGE_FMA(u2, __int_as_float(r2.y))
        EDGE_FMA(u3, __int_as_float(r3.y))
    }
    for (; j < deg; ++j) {
        int2 r = __ldg(&bin[j]);
        uint2 u = __ldg(&xr[(size_t)r.x * 32 + lane]);
        EDGE_FMA(u, __int_as_float(r.y))
    }
#undef EDGE_FMA

    float inv = 1.f / fmaxf(cm, 1.f);
    __half2 h0 = __floats2half2_rn(acc.x * inv, acc.y * inv);
    __half2 h1 = __floats2half2_rn(acc.z * inv, acc.w * inv);
    g_meanh[(size_t)g * 32 + lane] = make_uint2(*(u32*)&h0, *(u32*)&h1);
}

// ---------------------------------------------------------------------------
// K5: fused HMMA GEMM + relu + LN + mask (unchanged from round 5).
// ---------------------------------------------------------------------------
#define FUSED_THREADS 256
#define IN_PITCH 264
#define W_PITCH_H 136
#define SMEM_WH_BYTES (256 * W_PITCH_H * 2)
#define SMEM_IN_BYTES (128 * IN_PITCH * 2)
#define SMEM_CONST_BYTES (3 * 128 * 4)
#define FUSED_SMEM_BYTES (SMEM_WH_BYTES + SMEM_IN_BYTES + SMEM_CONST_BYTES)
#define NTILES ((NB + 127) / 128)             // 313

__device__ __forceinline__ u32 smem_u32(const void* p) {
    u32 a;
    asm("{ .reg .u64 t; cvta.to.shared.u64 t, %1; cvt.u32.u64 %0, t; }"
        : "=r"(a) : "l"(p));
    return a;
}
__device__ __forceinline__ void ldsm_x4(u32& r0, u32& r1, u32& r2, u32& r3, u32 a) {
    asm volatile("ldmatrix.sync.aligned.m8n8.x4.shared.b16 {%0,%1,%2,%3}, [%4];"
                 : "=r"(r0), "=r"(r1), "=r"(r2), "=r"(r3) : "r"(a));
}
__device__ __forceinline__ void ldsm_x4t(u32& r0, u32& r1, u32& r2, u32& r3, u32 a) {
    asm volatile("ldmatrix.sync.aligned.m8n8.x4.trans.shared.b16 {%0,%1,%2,%3}, [%4];"
                 : "=r"(r0), "=r"(r1), "=r"(r2), "=r"(r3) : "r"(a));
}
__device__ __forceinline__ void mma16816(float* c, u32 a0, u32 a1, u32 a2, u32 a3,
                                         u32 b0, u32 b1) {
    asm volatile(
        "mma.sync.aligned.m16n8k16.row.col.f32.f16.f16.f32 "
        "{%0,%1,%2,%3}, {%4,%5,%6,%7}, {%8,%9}, {%0,%1,%2,%3};"
        : "+f"(c[0]), "+f"(c[1]), "+f"(c[2]), "+f"(c[3])
        : "r"(a0), "r"(a1), "r"(a2), "r"(a3), "r"(b0), "r"(b1));
}

__global__ void __launch_bounds__(FUSED_THREADS, 1)
fused_kernel(const float* __restrict__ Wself,
             const float* __restrict__ bself,
             const float* __restrict__ Wnb,
             const float* __restrict__ bnb,
             const float* __restrict__ gamma,
             const float* __restrict__ beta,
             const float* __restrict__ nmask,
             float* __restrict__ out) {
    extern __shared__ char sm[];
    __half* Wh = (__half*)sm;
    __half* inSh = (__half*)(sm + SMEM_WH_BYTES);
    float* bias_sm = (float*)(sm + SMEM_WH_BYTES + SMEM_IN_BYTES);
    float* gm_sm = bias_sm + 128;
    float* bt_sm = gm_sm + 128;

    const int tid = threadIdx.x;
    const int lane = tid & 31;
    const int wid = tid >> 5;

    for (int i = tid; i < 256 * 128; i += FUSED_THREADS) {
        int k = i >> 7;
        int n = i & 127;
        float w = (k < 128) ? __ldg(&Wself[k * 128 + n])
                            : __ldg(&Wnb[(k - 128) * 128 + n]);
        Wh[k * W_PITCH_H + n] = __float2half_rn(w);
    }
    if (tid < 128) {
        bias_sm[tid] = __ldg(&bself[tid]) + __ldg(&bnb[tid]);
        gm_sm[tid] = __ldg(&gamma[tid]);
        bt_sm[tid] = __ldg(&beta[tid]);
    }
    __syncthreads();

    const u32 in_u = smem_u32(inSh);
    const u32 wh_u = smem_u32(Wh);
    const u32 a_row_off = (u32)(wid * 16 + (lane & 15)) * (IN_PITCH * 2)
                        + (u32)((lane >> 4) * 8) * 2;
    const u32 b_row_lane = (u32)(lane & 15) * (W_PITCH_H * 2);
    const u32 b_col_lane = (u32)((lane >> 4) * 8) * 2;

    for (int tile = blockIdx.x; tile < NTILES; tile += gridDim.x) {
        const int node0 = tile * 128;

        for (int i = tid; i < 128 * 64; i += FUSED_THREADS) {
            int nl = i >> 6;
            int c = i & 63;
            int gn = node0 + nl;
            uint2 v = make_uint2(0u, 0u);
            if (gn < NB)
                v = (c < 32) ? __ldg(&g_xh[(size_t)gn * 32 + c])
                             : __ldg(&g_meanh[(size_t)gn * 32 + (c - 32)]);
            *(uint2*)((char*)inSh + (size_t)nl * (IN_PITCH * 2) + (size_t)c * 8) = v;
        }
        __syncthreads();

        float acc[16][4];
#pragma unroll
        for (int j = 0; j < 16; ++j) {
            float2 bv = *(float2*)&bias_sm[j * 8 + (lane & 3) * 2];
            acc[j][0] = bv.x; acc[j][1] = bv.y;
            acc[j][2] = bv.x; acc[j][3] = bv.y;
        }

#pragma unroll 1
        for (int ks = 0; ks < 16; ++ks) {
            u32 a0, a1, a2, a3;
            ldsm_x4(a0, a1, a2, a3, in_u + a_row_off + (u32)ks * 32);
            u32 brow = wh_u + (u32)ks * 16 * (W_PITCH_H * 2) + b_row_lane + b_col_lane;
#pragma unroll
            for (int jt = 0; jt < 8; ++jt) {
                u32 b0, b1, b2, b3;
                ldsm_x4t(b0, b1, b2, b3, brow + (u32)jt * 32);
                mma16816(acc[2 * jt], a0, a1, a2, a3, b0, b1);
                mma16816(acc[2 * jt + 1], a0, a1, a2, a3, b2, b3);
            }
        }

#pragma unroll
        for (int j = 0; j < 16; ++j) {
            acc[j][0] = fmaxf(acc[j][0], 0.f);
            acc[j][1] = fmaxf(acc[j][1], 0.f);
            acc[j][2] = fmaxf(acc[j][2], 0.f);
            acc[j][3] = fmaxf(acc[j][3], 0.f);
        }
        float s0 = 0.f, s1 = 0.f;
#pragma unroll
        for (int j = 0; j < 16; ++j) {
            s0 += acc[j][0] + acc[j][1];
            s1 += acc[j][2] + acc[j][3];
        }
        s0 += __shfl_xor_sync(0xFFFFFFFFu, s0, 1);
        s0 += __shfl_xor_sync(0xFFFFFFFFu, s0, 2);
        s1 += __shfl_xor_sync(0xFFFFFFFFu, s1, 1);
        s1 += __shfl_xor_sync(0xFFFFFFFFu, s1, 2);
        float mu0 = s0 * (1.f / 128.f);
        float mu1 = s1 * (1.f / 128.f);

        float v0 = 0.f, v1 = 0.f;
#pragma unroll
        for (int j = 0; j < 16; ++j) {
            float d0 = acc[j][0] - mu0, d1 = acc[j][1] - mu0;
            float d2 = acc[j][2] - mu1, d3 = acc[j][3] - mu1;
            v0 += d0 * d0 + d1 * d1;
            v1 += d2 * d2 + d3 * d3;
        }
        v0 += __shfl_xor_sync(0xFFFFFFFFu, v0, 1);
        v0 += __shfl_xor_sync(0xFFFFFFFFu, v0, 2);
        v1 += __shfl_xor_sync(0xFFFFFFFFu, v1, 1);
        v1 += __shfl_xor_sync(0xFFFFFFFFu, v1, 2);
        float rstd0 = rsqrtf(v0 * (1.f / 128.f) + 1e-5f);
        float rstd1 = rsqrtf(v1 * (1.f / 128.f) + 1e-5f);

        int r0 = node0 + wid * 16 + (lane >> 2);
        int r1 = r0 + 8;
        float mk0 = (r0 < NB) ? __ldg(&nmask[r0]) : 0.f;
        float mk1 = (r1 < NB) ? __ldg(&nmask[r1]) : 0.f;
        float a0s = rstd0 * mk0, a1s = rstd1 * mk1;

#pragma unroll
        for (int j = 0; j < 16; ++j) {
            int col = j * 8 + (lane & 3) * 2;
            float2 g2 = *(float2*)&gm_sm[col];
            float2 b2 = *(float2*)&bt_sm[col];
            if (r0 < NB) {
                float2 o;
                o.x = ((acc[j][0] - mu0) * g2.x * a0s) + b2.x * mk0;
                o.y = ((acc[j][1] - mu0) * g2.y * a0s) + b2.y * mk0;
                *(float2*)&out[(size_t)r0 * 128 + col] = o;
            }
            if (r1 < NB) {
                float2 o;
                o.x = ((acc[j][2] - mu1) * g2.x * a1s) + b2.x * mk1;
                o.y = ((acc[j][3] - mu1) * g2.y * a1s) + b2.y * mk1;
                *(float2*)&out[(size_t)r1 * 128 + col] = o;
            }
        }
        __syncthreads();
    }
}

// ---------------------------------------------------------------------------
extern "C" void kernel_launch(void* const* d_in, const int* in_sizes, int n_in,
                              void* d_out, int out_size) {
    const float* x     = (const float*)d_in[0];
    const int*   ei    = (const int*)d_in[1];
    const float* nmask = (const float*)d_in[2];
    const float* emask = (const float*)d_in[3];
    const float* Wself = (const float*)d_in[4];
    const float* bself = (const float*)d_in[5];
    const float* Wnb   = (const float*)d_in[6];
    const float* bnb   = (const float*)d_in[7];
    const float* gamma = (const float*)d_in[8];
    const float* beta  = (const float*)d_in[9];
    float* out = (float*)d_out;

    (void)in_sizes; (void)n_in; (void)out_size;

    hist_prep_kernel<<<HIST_BLOCKS + PREP_BLOCKS, 256>>>(x, ei);
    scan_kernel<<<1, 1024>>>();
    fill_kernel<<<(NE / 8 + 255) / 256, 256>>>(ei, emask);
    gather_kernel<<<(NB * 32 + 255) / 256, 256>>>();

    cudaFuncSetAttribute(fused_kernel, cudaFuncAttributeMaxDynamicSharedMemorySize,
                         FUSED_SMEM_BYTES);
    int nsm = 148;
    cudaDeviceGetAttribute(&nsm, cudaDevAttrMultiProcessorCount, 0);
    fused_kernel<<<nsm, FUSED_THREADS, FUSED_SMEM_BYTES>>>(
        Wself, bself, Wnb, bnb, gamma, beta, nmask, out);
}

// round 9
// speedup vs baseline: 1.3116x; 1.3116x over previous
#include <cuda_runtime.h>
#include <cuda_fp16.h>

#define BB 8
#define NN 5000
#define EE 100000
#define DD 128
#define NB (BB * NN)        // 40000
#define NE (BB * EE)        // 800000

typedef unsigned long long u64;
typedef unsigned int u32;

// Scratch (allocation-free: __device__ globals)
__device__ __align__(16) int   g_deg[NB];
__device__ __align__(16) int   g_off[NB];
__device__ __align__(16) int   g_cursor[NB];
__device__ __align__(16) int2  g_bin[NE];
__device__ __align__(16) uint2 g_xh[NB * DD / 4];     // x as 4xhalf chunks
__device__ __align__(16) uint2 g_meanh[NB * DD / 4];  // mean as 4xhalf chunks

// ---------------------------------------------------------------------------
// K0: zero degree counters + convert x -> fp16   (round-5 proven)
// ---------------------------------------------------------------------------
__global__ void prep_kernel(const float* __restrict__ x) {
    int i = blockIdx.x * blockDim.x + threadIdx.x;
    if (i < NB) g_deg[i] = 0;
    if (i < NB * DD / 4) {
        float4 v = __ldg(&((const float4*)x)[i]);
        __half2 h0 = __floats2half2_rn(v.x, v.y);
        __half2 h1 = __floats2half2_rn(v.z, v.w);
        g_xh[i] = make_uint2(*(u32*)&h0, *(u32*)&h1);
    }
}

// ---------------------------------------------------------------------------
// K1: histogram of edge targets (4 edges/thread)   (round-5 proven)
// ---------------------------------------------------------------------------
__global__ void hist_kernel(const int* __restrict__ ei) {
    int t = blockIdx.x * blockDim.x + threadIdx.x;
    int base = t * 4;
    if (base >= NE) return;
    int b = base / EE;
    int e = base - b * EE;
    int4 t4 = __ldg((const int4*)&ei[(size_t)b * 2 * EE + EE + e]);
    int* deg = g_deg + b * NN;
    atomicAdd(&deg[t4.x], 1);
    atomicAdd(&deg[t4.y], 1);
    atomicAdd(&deg[t4.z], 1);
    atomicAdd(&deg[t4.w], 1);
}

// ---------------------------------------------------------------------------
// K2: exclusive prefix sum over 40000 degrees   (round-5 proven)
// ---------------------------------------------------------------------------
__global__ void __launch_bounds__(1024, 1) scan_kernel() {
    __shared__ int part[1024];
    const int t = threadIdx.x;
    const int CH = 40;
    int lo = t * CH;
    if (lo < NB) {
        const int4* d4 = (const int4*)(g_deg + lo);
        int s = 0;
#pragma unroll
        for (int i = 0; i < CH / 4; ++i) {
            int4 v = d4[i];
            s += v.x + v.y + v.z + v.w;
        }
        part[t] = s;
    } else {
        part[t] = 0;
    }
    __syncthreads();

    for (int o = 1; o < 1024; o <<= 1) {
        int v = (t >= o) ? part[t - o] : 0;
        __syncthreads();
        part[t] += v;
        __syncthreads();
    }

    if (lo < NB) {
        int run = (t > 0) ? part[t - 1] : 0;
        const int4* d4 = (const int4*)(g_deg + lo);
        int4* o4 = (int4*)(g_off + lo);
        int4* c4 = (int4*)(g_cursor + lo);
#pragma unroll
        for (int i = 0; i < CH / 4; ++i) {
            int4 v = d4[i];
            int4 w;
            w.x = run; run += v.x;
            w.y = run; run += v.y;
            w.z = run; run += v.z;
            w.w = run; run += v.w;
            o4[i] = w;
            c4[i] = w;
        }
    }
}

// ---------------------------------------------------------------------------
// K3: fill bins (4 edges/thread)   (round-5 proven)
// ---------------------------------------------------------------------------
__global__ void fill_kernel(const int* __restrict__ ei,
                            const float* __restrict__ em) {
    int t = blockIdx.x * blockDim.x + threadIdx.x;
    int base = t * 4;
    if (base >= NE) return;
    int b = base / EE;
    int e = base - b * EE;
    const int* eb = ei + (size_t)b * 2 * EE;
    int4 s4 = __ldg((const int4*)&eb[e]);
    int4 t4 = __ldg((const int4*)&eb[EE + e]);
    float4 m4 = __ldg((const float4*)&em[(size_t)b * EE + e]);
    int* cur = g_cursor + b * NN;
    int p0 = atomicAdd(&cur[t4.x], 1);
    int p1 = atomicAdd(&cur[t4.y], 1);
    int p2 = atomicAdd(&cur[t4.z], 1);
    int p3 = atomicAdd(&cur[t4.w], 1);
    g_bin[p0] = make_int2(s4.x, __float_as_int(m4.x));
    g_bin[p1] = make_int2(s4.y, __float_as_int(m4.y));
    g_bin[p2] = make_int2(s4.z, __float_as_int(m4.z));
    g_bin[p3] = make_int2(s4.w, __float_as_int(m4.w));
}

// ---------------------------------------------------------------------------
// K4: gather — NEW high-MLP shape. One warp per node.
// Edge records for the node are loaded lane-parallel in ONE coalesced LDG
// (lane l -> record l), then broadcast via shfl (26cyc, off the L2 path).
// Row loads are issued in predicated sub-chunks of 8 with uniform early-exit:
// no per-edge bin load, ~16-20 row loads in flight per warp.
// ---------------------------------------------------------------------------
__global__ void gather_kernel() {
    int g = (blockIdx.x * blockDim.x + threadIdx.x) >> 5;
    int lane = threadIdx.x & 31;
    if (g >= NB) return;
    int b = g / NN;

    const int deg = g_deg[g];
    const int off = g_off[g];
    const uint2* xr = g_xh + (size_t)b * NN * 32;
    const int2* bin = g_bin + off;

    float4 acc = make_float4(0.f, 0.f, 0.f, 0.f);
    float cm = 0.f;

    for (int base = 0; base < deg; base += 32) {
        int chunk = deg - base;
        if (chunk > 32) chunk = 32;
        int2 rec = make_int2(0, 0);
        if (lane < chunk) rec = __ldg(&bin[base + lane]);

#pragma unroll
        for (int j0 = 0; j0 < 32; j0 += 8) {
            if (j0 >= chunk) break;          // warp-uniform exit between groups
#pragma unroll
            for (int j = j0; j < j0 + 8; ++j) {
                int s = __shfl_sync(0xFFFFFFFFu, rec.x, j);
                float m = __int_as_float(__shfl_sync(0xFFFFFFFFu, rec.y, j));
                if (j < chunk) {             // warp-uniform predicate
                    uint2 u = __ldg(&xr[(u32)s * 32 + lane]);
                    float2 a = __half22float2(*(__half2*)&u.x);
                    float2 c = __half22float2(*(__half2*)&u.y);
                    acc.x = fmaf(a.x, m, acc.x);
                    acc.y = fmaf(a.y, m, acc.y);
                    acc.z = fmaf(c.x, m, acc.z);
                    acc.w = fmaf(c.y, m, acc.w);
                    cm += m;
                }
            }
        }
    }

    float inv = 1.f / fmaxf(cm, 1.f);
    __half2 h0 = __floats2half2_rn(acc.x * inv, acc.y * inv);
    __half2 h1 = __floats2half2_rn(acc.z * inv, acc.w * inv);
    g_meanh[(size_t)g * 32 + lane] = make_uint2(*(u32*)&h0, *(u32*)&h1);
}

// ---------------------------------------------------------------------------
// K5: fused HMMA GEMM + relu + LN + mask (unchanged from round 5).
// ---------------------------------------------------------------------------
#define FUSED_THREADS 256
#define IN_PITCH 264
#define W_PITCH_H 136
#define SMEM_WH_BYTES (256 * W_PITCH_H * 2)
#define SMEM_IN_BYTES (128 * IN_PITCH * 2)
#define SMEM_CONST_BYTES (3 * 128 * 4)
#define FUSED_SMEM_BYTES (SMEM_WH_BYTES + SMEM_IN_BYTES + SMEM_CONST_BYTES)
#define NTILES ((NB + 127) / 128)             // 313

__device__ __forceinline__ u32 smem_u32(const void* p) {
    u32 a;
    asm("{ .reg .u64 t; cvta.to.shared.u64 t, %1; cvt.u32.u64 %0, t; }"
        : "=r"(a) : "l"(p));
    return a;
}
__device__ __forceinline__ void ldsm_x4(u32& r0, u32& r1, u32& r2, u32& r3, u32 a) {
    asm volatile("ldmatrix.sync.aligned.m8n8.x4.shared.b16 {%0,%1,%2,%3}, [%4];"
                 : "=r"(r0), "=r"(r1), "=r"(r2), "=r"(r3) : "r"(a));
}
__device__ __forceinline__ void ldsm_x4t(u32& r0, u32& r1, u32& r2, u32& r3, u32 a) {
    asm volatile("ldmatrix.sync.aligned.m8n8.x4.trans.shared.b16 {%0,%1,%2,%3}, [%4];"
                 : "=r"(r0), "=r"(r1), "=r"(r2), "=r"(r3) : "r"(a));
}
__device__ __forceinline__ void mma16816(float* c, u32 a0, u32 a1, u32 a2, u32 a3,
                                         u32 b0, u32 b1) {
    asm volatile(
        "mma.sync.aligned.m16n8k16.row.col.f32.f16.f16.f32 "
        "{%0,%1,%2,%3}, {%4,%5,%6,%7}, {%8,%9}, {%0,%1,%2,%3};"
        : "+f"(c[0]), "+f"(c[1]), "+f"(c[2]), "+f"(c[3])
        : "r"(a0), "r"(a1), "r"(a2), "r"(a3), "r"(b0), "r"(b1));
}

__global__ void __launch_bounds__(FUSED_THREADS, 1)
fused_kernel(const float* __restrict__ Wself,
             const float* __restrict__ bself,
             const float* __restrict__ Wnb,
             const float* __restrict__ bnb,
             const float* __restrict__ gamma,
             const float* __restrict__ beta,
             const float* __restrict__ nmask,
             float* __restrict__ out) {
    extern __shared__ char sm[];
    __half* Wh = (__half*)sm;
    __half* inSh = (__half*)(sm + SMEM_WH_BYTES);
    float* bias_sm = (float*)(sm + SMEM_WH_BYTES + SMEM_IN_BYTES);
    float* gm_sm = bias_sm + 128;
    float* bt_sm = gm_sm + 128;

    const int tid = threadIdx.x;
    const int lane = tid & 31;
    const int wid = tid >> 5;

    for (int i = tid; i < 256 * 128; i += FUSED_THREADS) {
        int k = i >> 7;
        int n = i & 127;
        float w = (k < 128) ? __ldg(&Wself[k * 128 + n])
                            : __ldg(&Wnb[(k - 128) * 128 + n]);
        Wh[k * W_PITCH_H + n] = __float2half_rn(w);
    }
    if (tid < 128) {
        bias_sm[tid] = __ldg(&bself[tid]) + __ldg(&bnb[tid]);
        gm_sm[tid] = __ldg(&gamma[tid]);
        bt_sm[tid] = __ldg(&beta[tid]);
    }
    __syncthreads();

    const u32 in_u = smem_u32(inSh);
    const u32 wh_u = smem_u32(Wh);
    const u32 a_row_off = (u32)(wid * 16 + (lane & 15)) * (IN_PITCH * 2)
                        + (u32)((lane >> 4) * 8) * 2;
    const u32 b_row_lane = (u32)(lane & 15) * (W_PITCH_H * 2);
    const u32 b_col_lane = (u32)((lane >> 4) * 8) * 2;

    for (int tile = blockIdx.x; tile < NTILES; tile += gridDim.x) {
        const int node0 = tile * 128;

        for (int i = tid; i < 128 * 64; i += FUSED_THREADS) {
            int nl = i >> 6;
            int c = i & 63;
            int gn = node0 + nl;
            uint2 v = make_uint2(0u, 0u);
            if (gn < NB)
                v = (c < 32) ? __ldg(&g_xh[(size_t)gn * 32 + c])
                             : __ldg(&g_meanh[(size_t)gn * 32 + (c - 32)]);
            *(uint2*)((char*)inSh + (size_t)nl * (IN_PITCH * 2) + (size_t)c * 8) = v;
        }
        __syncthreads();

        float acc[16][4];
#pragma unroll
        for (int j = 0; j < 16; ++j) {
            float2 bv = *(float2*)&bias_sm[j * 8 + (lane & 3) * 2];
            acc[j][0] = bv.x; acc[j][1] = bv.y;
            acc[j][2] = bv.x; acc[j][3] = bv.y;
        }

#pragma unroll 1
        for (int ks = 0; ks < 16; ++ks) {
            u32 a0, a1, a2, a3;
            ldsm_x4(a0, a1, a2, a3, in_u + a_row_off + (u32)ks * 32);
            u32 brow = wh_u + (u32)ks * 16 * (W_PITCH_H * 2) + b_row_lane + b_col_lane;
#pragma unroll
            for (int jt = 0; jt < 8; ++jt) {
                u32 b0, b1, b2, b3;
                ldsm_x4t(b0, b1, b2, b3, brow + (u32)jt * 32);
                mma16816(acc[2 * jt], a0, a1, a2, a3, b0, b1);
                mma16816(acc[2 * jt + 1], a0, a1, a2, a3, b2, b3);
            }
        }

#pragma unroll
        for (int j = 0; j < 16; ++j) {
            acc[j][0] = fmaxf(acc[j][0], 0.f);
            acc[j][1] = fmaxf(acc[j][1], 0.f);
            acc[j][2] = fmaxf(acc[j][2], 0.f);
            acc[j][3] = fmaxf(acc[j][3], 0.f);
        }
        float s0 = 0.f, s1 = 0.f;
#pragma unroll
        for (int j = 0; j < 16; ++j) {
            s0 += acc[j][0] + acc[j][1];
            s1 += acc[j][2] + acc[j][3];
        }
        s0 += __shfl_xor_sync(0xFFFFFFFFu, s0, 1);
        s0 += __shfl_xor_sync(0xFFFFFFFFu, s0, 2);
        s1 += __shfl_xor_sync(0xFFFFFFFFu, s1, 1);
        s1 += __shfl_xor_sync(0xFFFFFFFFu, s1, 2);
        float mu0 = s0 * (1.f / 128.f);
        float mu1 = s1 * (1.f / 128.f);

        float v0 = 0.f, v1 = 0.f;
#pragma unroll
        for (int j = 0; j < 16; ++j) {
            float d0 = acc[j][0] - mu0, d1 = acc[j][1] - mu0;
            float d2 = acc[j][2] - mu1, d3 = acc[j][3] - mu1;
            v0 += d0 * d0 + d1 * d1;
            v1 += d2 * d2 + d3 * d3;
        }
        v0 += __shfl_xor_sync(0xFFFFFFFFu, v0, 1);
        v0 += __shfl_xor_sync(0xFFFFFFFFu, v0, 2);
        v1 += __shfl_xor_sync(0xFFFFFFFFu, v1, 1);
        v1 += __shfl_xor_sync(0xFFFFFFFFu, v1, 2);
        float rstd0 = rsqrtf(v0 * (1.f / 128.f) + 1e-5f);
        float rstd1 = rsqrtf(v1 * (1.f / 128.f) + 1e-5f);

        int r0 = node0 + wid * 16 + (lane >> 2);
        int r1 = r0 + 8;
        float mk0 = (r0 < NB) ? __ldg(&nmask[r0]) : 0.f;
        float mk1 = (r1 < NB) ? __ldg(&nmask[r1]) : 0.f;
        float a0s = rstd0 * mk0, a1s = rstd1 * mk1;

#pragma unroll
        for (int j = 0; j < 16; ++j) {
            int col = j * 8 + (lane & 3) * 2;
            float2 g2 = *(float2*)&gm_sm[col];
            float2 b2 = *(float2*)&bt_sm[col];
            if (r0 < NB) {
                float2 o;
                o.x = ((acc[j][0] - mu0) * g2.x * a0s) + b2.x * mk0;
                o.y = ((acc[j][1] - mu0) * g2.y * a0s) + b2.y * mk0;
                *(float2*)&out[(size_t)r0 * 128 + col] = o;
            }
            if (r1 < NB) {
                float2 o;
                o.x = ((acc[j][2] - mu1) * g2.x * a1s) + b2.x * mk1;
                o.y = ((acc[j][3] - mu1) * g2.y * a1s) + b2.y * mk1;
                *(float2*)&out[(size_t)r1 * 128 + col] = o;
            }
        }
        __syncthreads();
    }
}

// ---------------------------------------------------------------------------
extern "C" void kernel_launch(void* const* d_in, const int* in_sizes, int n_in,
                              void* d_out, int out_size) {
    const float* x     = (const float*)d_in[0];
    const int*   ei    = (const int*)d_in[1];
    const float* nmask = (const float*)d_in[2];
    const float* emask = (const float*)d_in[3];
    const float* Wself = (const float*)d_in[4];
    const float* bself = (const float*)d_in[5];
    const float* Wnb   = (const float*)d_in[6];
    const float* bnb   = (const float*)d_in[7];
    const float* gamma = (const float*)d_in[8];
    const float* beta  = (const float*)d_in[9];
    float* out = (float*)d_out;

    (void)in_sizes; (void)n_in; (void)out_size;

    prep_kernel<<<(NB * DD / 4 + 255) / 256, 256>>>(x);
    hist_kernel<<<(NE / 4 + 255) / 256, 256>>>(ei);
    scan_kernel<<<1, 1024>>>();
    fill_kernel<<<(NE / 4 + 255) / 256, 256>>>(ei, emask);
    gather_kernel<<<(NB * 32 + 255) / 256, 256>>>();

    cudaFuncSetAttribute(fused_kernel, cudaFuncAttributeMaxDynamicSharedMemorySize,
                         FUSED_SMEM_BYTES);
    int nsm = 148;
    cudaDeviceGetAttribute(&nsm, cudaDevAttrMultiProcessorCount, 0);
    fused_kernel<<<nsm, FUSED_THREADS, FUSED_SMEM_BYTES>>>(
        Wself, bself, Wnb, bnb, gamma, beta, nmask, out);
}

// round 10
// speedup vs baseline: 1.3477x; 1.0275x over previous
#include <cuda_runtime.h>
#include <cuda_fp16.h>

#define BB 8
#define NN 5000
#define EE 100000
#define DD 128
#define NB (BB * NN)        // 40000
#define NE (BB * EE)        // 800000

typedef unsigned long long u64;
typedef unsigned int u32;

// Scratch (allocation-free: __device__ globals)
__device__ __align__(16) int   g_deg[NB];
__device__ __align__(16) int   g_off[NB];
__device__ __align__(16) int   g_cursor[NB];
__device__ __align__(16) int2  g_bin[NE];
__device__ __align__(16) uint2 g_xh[NB * DD / 4];     // x as 4xhalf chunks
__device__ __align__(16) uint2 g_meanh[NB * DD / 4];  // mean as 4xhalf chunks

// ---------------------------------------------------------------------------
// K0: zero degree counters + convert x -> fp16   (round-5 proven)
// ---------------------------------------------------------------------------
__global__ void prep_kernel(const float* __restrict__ x) {
    int i = blockIdx.x * blockDim.x + threadIdx.x;
    if (i < NB) g_deg[i] = 0;
    if (i < NB * DD / 4) {
        float4 v = __ldg(&((const float4*)x)[i]);
        __half2 h0 = __floats2half2_rn(v.x, v.y);
        __half2 h1 = __floats2half2_rn(v.z, v.w);
        g_xh[i] = make_uint2(*(u32*)&h0, *(u32*)&h1);
    }
}

// ---------------------------------------------------------------------------
// K1: histogram of edge targets (4 edges/thread)   (round-5 proven)
// ---------------------------------------------------------------------------
__global__ void hist_kernel(const int* __restrict__ ei) {
    int t = blockIdx.x * blockDim.x + threadIdx.x;
    int base = t * 4;
    if (base >= NE) return;
    int b = base / EE;
    int e = base - b * EE;
    int4 t4 = __ldg((const int4*)&ei[(size_t)b * 2 * EE + EE + e]);
    int* deg = g_deg + b * NN;
    atomicAdd(&deg[t4.x], 1);
    atomicAdd(&deg[t4.y], 1);
    atomicAdd(&deg[t4.z], 1);
    atomicAdd(&deg[t4.w], 1);
}

// ---------------------------------------------------------------------------
// K2: exclusive prefix sum over 40000 degrees   (round-5 proven)
// ---------------------------------------------------------------------------
__global__ void __launch_bounds__(1024, 1) scan_kernel() {
    __shared__ int part[1024];
    const int t = threadIdx.x;
    const int CH = 40;
    int lo = t * CH;
    if (lo < NB) {
        const int4* d4 = (const int4*)(g_deg + lo);
        int s = 0;
#pragma unroll
        for (int i = 0; i < CH / 4; ++i) {
            int4 v = d4[i];
            s += v.x + v.y + v.z + v.w;
        }
        part[t] = s;
    } else {
        part[t] = 0;
    }
    __syncthreads();

    for (int o = 1; o < 1024; o <<= 1) {
        int v = (t >= o) ? part[t - o] : 0;
        __syncthreads();
        part[t] += v;
        __syncthreads();
    }

    if (lo < NB) {
        int run = (t > 0) ? part[t - 1] : 0;
        const int4* d4 = (const int4*)(g_deg + lo);
        int4* o4 = (int4*)(g_off + lo);
        int4* c4 = (int4*)(g_cursor + lo);
#pragma unroll
        for (int i = 0; i < CH / 4; ++i) {
            int4 v = d4[i];
            int4 w;
            w.x = run; run += v.x;
            w.y = run; run += v.y;
            w.z = run; run += v.z;
            w.w = run; run += v.w;
            o4[i] = w;
            c4[i] = w;
        }
    }
}

// ---------------------------------------------------------------------------
// K3: fill bins (4 edges/thread)   (round-5 proven)
// ---------------------------------------------------------------------------
__global__ void fill_kernel(const int* __restrict__ ei,
                            const float* __restrict__ em) {
    int t = blockIdx.x * blockDim.x + threadIdx.x;
    int base = t * 4;
    if (base >= NE) return;
    int b = base / EE;
    int e = base - b * EE;
    const int* eb = ei + (size_t)b * 2 * EE;
    int4 s4 = __ldg((const int4*)&eb[e]);
    int4 t4 = __ldg((const int4*)&eb[EE + e]);
    float4 m4 = __ldg((const float4*)&em[(size_t)b * EE + e]);
    int* cur = g_cursor + b * NN;
    int p0 = atomicAdd(&cur[t4.x], 1);
    int p1 = atomicAdd(&cur[t4.y], 1);
    int p2 = atomicAdd(&cur[t4.z], 1);
    int p3 = atomicAdd(&cur[t4.w], 1);
    g_bin[p0] = make_int2(s4.x, __float_as_int(m4.x));
    g_bin[p1] = make_int2(s4.y, __float_as_int(m4.y));
    g_bin[p2] = make_int2(s4.z, __float_as_int(m4.z));
    g_bin[p3] = make_int2(s4.w, __float_as_int(m4.w));
}

// ---------------------------------------------------------------------------
// K4: gather — depth-2 software pipeline. One warp per node, lane owns a
// uint2 (4 halfs) of the 256B row (round-5 shape). Batches of 4 edges:
//   iteration i issues rec loads for batch i+2 and row loads for batch i+1,
//   then consumes batch i. Loads issued in iter i are consumed in iter i+1,
//   so ptxas CANNOT serialize them (round-8 evidence: regs=34 had collapsed
//   the flat unroll to MLP~1, each edge paying full L2 latency).
// ---------------------------------------------------------------------------
__global__ void gather_kernel() {
    int g = (blockIdx.x * blockDim.x + threadIdx.x) >> 5;
    int lane = threadIdx.x & 31;
    if (g >= NB) return;
    int b = g / NN;

    const int deg = g_deg[g];
    const int off = g_off[g];
    const uint2* xr = g_xh + (size_t)b * NN * 32;
    const int2* bin = g_bin + off;

    float4 acc = make_float4(0.f, 0.f, 0.f, 0.f);
    float cm = 0.f;

#define EDGE_FMA(u, m)                                                        \
    {                                                                         \
        float2 a = __half22float2(*(__half2*)&(u).x);                         \
        float2 c = __half22float2(*(__half2*)&(u).y);                         \
        acc.x = fmaf(a.x, (m), acc.x);                                        \
        acc.y = fmaf(a.y, (m), acc.y);                                        \
        acc.z = fmaf(c.x, (m), acc.z);                                        \
        acc.w = fmaf(c.y, (m), acc.w);                                        \
        cm += (m);                                                            \
    }

    const int nb = deg >> 2;   // number of full 4-edge batches
    if (nb > 0) {
        int2 ra[4], rb[4];
        uint2 ua[4];
        // prologue: recs for batches 0 and 1; rows for batch 0
#pragma unroll
        for (int k = 0; k < 4; ++k) ra[k] = __ldg(&bin[k]);
        if (nb > 1) {
#pragma unroll
            for (int k = 0; k < 4; ++k) rb[k] = __ldg(&bin[4 + k]);
        }
#pragma unroll
        for (int k = 0; k < 4; ++k)
            ua[k] = __ldg(&xr[(u32)ra[k].x * 32 + lane]);

        for (int i = 0; i < nb; ++i) {
            int2 rc[4];
            uint2 ub[4];
            if (i + 2 < nb) {              // prefetch recs for batch i+2
#pragma unroll
                for (int k = 0; k < 4; ++k)
                    rc[k] = __ldg(&bin[(i + 2) * 4 + k]);
            }
            if (i + 1 < nb) {              // prefetch rows for batch i+1
#pragma unroll
                for (int k = 0; k < 4; ++k)
                    ub[k] = __ldg(&xr[(u32)rb[k].x * 32 + lane]);
            }
            // consume batch i
#pragma unroll
            for (int k = 0; k < 4; ++k)
                EDGE_FMA(ua[k], __int_as_float(ra[k].y))
            // shift pipeline
#pragma unroll
            for (int k = 0; k < 4; ++k) {
                ra[k] = rb[k];
                rb[k] = rc[k];
                ua[k] = ub[k];
            }
        }
    }
    // tail (< 4 edges)
    for (int j = nb * 4; j < deg; ++j) {
        int2 r = __ldg(&bin[j]);
        uint2 u = __ldg(&xr[(u32)r.x * 32 + lane]);
        EDGE_FMA(u, __int_as_float(r.y))
    }
#undef EDGE_FMA

    float inv = 1.f / fmaxf(cm, 1.f);
    __half2 h0 = __floats2half2_rn(acc.x * inv, acc.y * inv);
    __half2 h1 = __floats2half2_rn(acc.z * inv, acc.w * inv);
    g_meanh[(size_t)g * 32 + lane] = make_uint2(*(u32*)&h0, *(u32*)&h1);
}

// ---------------------------------------------------------------------------
// K5: fused HMMA GEMM + relu + LN + mask (unchanged from round 5).
// ---------------------------------------------------------------------------
#define FUSED_THREADS 256
#define IN_PITCH 264
#define W_PITCH_H 136
#define SMEM_WH_BYTES (256 * W_PITCH_H * 2)
#define SMEM_IN_BYTES (128 * IN_PITCH * 2)
#define SMEM_CONST_BYTES (3 * 128 * 4)
#define FUSED_SMEM_BYTES (SMEM_WH_BYTES + SMEM_IN_BYTES + SMEM_CONST_BYTES)
#define NTILES ((NB + 127) / 128)             // 313

__device__ __forceinline__ u32 smem_u32(const void* p) {
    u32 a;
    asm("{ .reg .u64 t; cvta.to.shared.u64 t, %1; cvt.u32.u64 %0, t; }"
        : "=r"(a) : "l"(p));
    return a;
}
__device__ __forceinline__ void ldsm_x4(u32& r0, u32& r1, u32& r2, u32& r3, u32 a) {
    asm volatile("ldmatrix.sync.aligned.m8n8.x4.shared.b16 {%0,%1,%2,%3}, [%4];"
                 : "=r"(r0), "=r"(r1), "=r"(r2), "=r"(r3) : "r"(a));
}
__device__ __forceinline__ void ldsm_x4t(u32& r0, u32& r1, u32& r2, u32& r3, u32 a) {
    asm volatile("ldmatrix.sync.aligned.m8n8.x4.trans.shared.b16 {%0,%1,%2,%3}, [%4];"
                 : "=r"(r0), "=r"(r1), "=r"(r2), "=r"(r3) : "r"(a));
}
__device__ __forceinline__ void mma16816(float* c, u32 a0, u32 a1, u32 a2, u32 a3,
                                         u32 b0, u32 b1) {
    asm volatile(
        "mma.sync.aligned.m16n8k16.row.col.f32.f16.f16.f32 "
        "{%0,%1,%2,%3}, {%4,%5,%6,%7}, {%8,%9}, {%0,%1,%2,%3};"
        : "+f"(c[0]), "+f"(c[1]), "+f"(c[2]), "+f"(c[3])
        : "r"(a0), "r"(a1), "r"(a2), "r"(a3), "r"(b0), "r"(b1));
}

__global__ void __launch_bounds__(FUSED_THREADS, 1)
fused_kernel(const float* __restrict__ Wself,
             const float* __restrict__ bself,
             const float* __restrict__ Wnb,
             const float* __restrict__ bnb,
             const float* __restrict__ gamma,
             const float* __restrict__ beta,
             const float* __restrict__ nmask,
             float* __restrict__ out) {
    extern __shared__ char sm[];
    __half* Wh = (__half*)sm;
    __half* inSh = (__half*)(sm + SMEM_WH_BYTES);
    float* bias_sm = (float*)(sm + SMEM_WH_BYTES + SMEM_IN_BYTES);
    float* gm_sm = bias_sm + 128;
    float* bt_sm = gm_sm + 128;

    const int tid = threadIdx.x;
    const int lane = tid & 31;
    const int wid = tid >> 5;

    for (int i = tid; i < 256 * 128; i += FUSED_THREADS) {
        int k = i >> 7;
        int n = i & 127;
        float w = (k < 128) ? __ldg(&Wself[k * 128 + n])
                            : __ldg(&Wnb[(k - 128) * 128 + n]);
        Wh[k * W_PITCH_H + n] = __float2half_rn(w);
    }
    if (tid < 128) {
        bias_sm[tid] = __ldg(&bself[tid]) + __ldg(&bnb[tid]);
        gm_sm[tid] = __ldg(&gamma[tid]);
        bt_sm[tid] = __ldg(&beta[tid]);
    }
    __syncthreads();

    const u32 in_u = smem_u32(inSh);
    const u32 wh_u = smem_u32(Wh);
    const u32 a_row_off = (u32)(wid * 16 + (lane & 15)) * (IN_PITCH * 2)
                        + (u32)((lane >> 4) * 8) * 2;
    const u32 b_row_lane = (u32)(lane & 15) * (W_PITCH_H * 2);
    const u32 b_col_lane = (u32)((lane >> 4) * 8) * 2;

    for (int tile = blockIdx.x; tile < NTILES; tile += gridDim.x) {
        const int node0 = tile * 128;

        for (int i = tid; i < 128 * 64; i += FUSED_THREADS) {
            int nl = i >> 6;
            int c = i & 63;
            int gn = node0 + nl;
            uint2 v = make_uint2(0u, 0u);
            if (gn < NB)
                v = (c < 32) ? __ldg(&g_xh[(size_t)gn * 32 + c])
                             : __ldg(&g_meanh[(size_t)gn * 32 + (c - 32)]);
            *(uint2*)((char*)inSh + (size_t)nl * (IN_PITCH * 2) + (size_t)c * 8) = v;
        }
        __syncthreads();

        float acc[16][4];
#pragma unroll
        for (int j = 0; j < 16; ++j) {
            float2 bv = *(float2*)&bias_sm[j * 8 + (lane & 3) * 2];
            acc[j][0] = bv.x; acc[j][1] = bv.y;
            acc[j][2] = bv.x; acc[j][3] = bv.y;
        }

#pragma unroll 1
        for (int ks = 0; ks < 16; ++ks) {
            u32 a0, a1, a2, a3;
            ldsm_x4(a0, a1, a2, a3, in_u + a_row_off + (u32)ks * 32);
            u32 brow = wh_u + (u32)ks * 16 * (W_PITCH_H * 2) + b_row_lane + b_col_lane;
#pragma unroll
            for (int jt = 0; jt < 8; ++jt) {
                u32 b0, b1, b2, b3;
                ldsm_x4t(b0, b1, b2, b3, brow + (u32)jt * 32);
                mma16816(acc[2 * jt], a0, a1, a2, a3, b0, b1);
                mma16816(acc[2 * jt + 1], a0, a1, a2, a3, b2, b3);
            }
        }

#pragma unroll
        for (int j = 0; j < 16; ++j) {
            acc[j][0] = fmaxf(acc[j][0], 0.f);
            acc[j][1] = fmaxf(acc[j][1], 0.f);
            acc[j][2] = fmaxf(acc[j][2], 0.f);
            acc[j][3] = fmaxf(acc[j][3], 0.f);
        }
        float s0 = 0.f, s1 = 0.f;
#pragma unroll
        for (int j = 0; j < 16; ++j) {
            s0 += acc[j][0] + acc[j][1];
            s1 += acc[j][2] + acc[j][3];
        }
        s0 += __shfl_xor_sync(0xFFFFFFFFu, s0, 1);
        s0 += __shfl_xor_sync(0xFFFFFFFFu, s0, 2);
        s1 += __shfl_xor_sync(0xFFFFFFFFu, s1, 1);
        s1 += __shfl_xor_sync(0xFFFFFFFFu, s1, 2);
        float mu0 = s0 * (1.f / 128.f);
        float mu1 = s1 * (1.f / 128.f);

        float v0 = 0.f, v1 = 0.f;
#pragma unroll
        for (int j = 0; j < 16; ++j) {
            float d0 = acc[j][0] - mu0, d1 = acc[j][1] - mu0;
            float d2 = acc[j][2] - mu1, d3 = acc[j][3] - mu1;
            v0 += d0 * d0 + d1 * d1;
            v1 += d2 * d2 + d3 * d3;
        }
        v0 += __shfl_xor_sync(0xFFFFFFFFu, v0, 1);
        v0 += __shfl_xor_sync(0xFFFFFFFFu, v0, 2);
        v1 += __shfl_xor_sync(0xFFFFFFFFu, v1, 1);
        v1 += __shfl_xor_sync(0xFFFFFFFFu, v1, 2);
        float rstd0 = rsqrtf(v0 * (1.f / 128.f) + 1e-5f);
        float rstd1 = rsqrtf(v1 * (1.f / 128.f) + 1e-5f);

        int r0 = node0 + wid * 16 + (lane >> 2);
        int r1 = r0 + 8;
        float mk0 = (r0 < NB) ? __ldg(&nmask[r0]) : 0.f;
        float mk1 = (r1 < NB) ? __ldg(&nmask[r1]) : 0.f;
        float a0s = rstd0 * mk0, a1s = rstd1 * mk1;

#pragma unroll
        for (int j = 0; j < 16; ++j) {
            int col = j * 8 + (lane & 3) * 2;
            float2 g2 = *(float2*)&gm_sm[col];
            float2 b2 = *(float2*)&bt_sm[col];
            if (r0 < NB) {
                float2 o;
                o.x = ((acc[j][0] - mu0) * g2.x * a0s) + b2.x * mk0;
                o.y = ((acc[j][1] - mu0) * g2.y * a0s) + b2.y * mk0;
                *(float2*)&out[(size_t)r0 * 128 + col] = o;
            }
            if (r1 < NB) {
                float2 o;
                o.x = ((acc[j][2] - mu1) * g2.x * a1s) + b2.x * mk1;
                o.y = ((acc[j][3] - mu1) * g2.y * a1s) + b2.y * mk1;
                *(float2*)&out[(size_t)r1 * 128 + col] = o;
            }
        }
        __syncthreads();
    }
}

// ---------------------------------------------------------------------------
extern "C" void kernel_launch(void* const* d_in, const int* in_sizes, int n_in,
                              void* d_out, int out_size) {
    const float* x     = (const float*)d_in[0];
    const int*   ei    = (const int*)d_in[1];
    const float* nmask = (const float*)d_in[2];
    const float* emask = (const float*)d_in[3];
    const float* Wself = (const float*)d_in[4];
    const float* bself = (const float*)d_in[5];
    const float* Wnb   = (const float*)d_in[6];
    const float* bnb   = (const float*)d_in[7];
    const float* gamma = (const float*)d_in[8];
    const float* beta  = (const float*)d_in[9];
    float* out = (float*)d_out;

    (void)in_sizes; (void)n_in; (void)out_size;

    prep_kernel<<<(NB * DD / 4 + 255) / 256, 256>>>(x);
    hist_kernel<<<(NE / 4 + 255) / 256, 256>>>(ei);
    scan_kernel<<<1, 1024>>>();
    fill_kernel<<<(NE / 4 + 255) / 256, 256>>>(ei, emask);
    gather_kernel<<<(NB * 32 + 255) / 256, 256>>>();

    cudaFuncSetAttribute(fused_kernel, cudaFuncAttributeMaxDynamicSharedMemorySize,
                         FUSED_SMEM_BYTES);
    int nsm = 148;
    cudaDeviceGetAttribute(&nsm, cudaDevAttrMultiProcessorCount, 0);
    fused_kernel<<<nsm, FUSED_THREADS, FUSED_SMEM_BYTES>>>(
        Wself, bself, Wnb, bnb, gamma, beta, nmask, out);
}